// round 15
// baseline (speedup 1.0000x reference)
#include <cuda_runtime.h>
#include <cuda_bf16.h>
#include <cuda_fp16.h>
#include <cstdint>

// Problem constants: B=2, H=16, S=2048, D=64
#define BB 2
#define HH 16
#define SEQ 2048
#define DIM 64
#define BH (BB*HH)

// Scratch: V transposed fp16 (8.4 MB) + raw scores fp16 (268 MB)
__device__ __half g_vT_f16[(size_t)BH * DIM * SEQ];
__device__ __half g_scores[(size_t)BH * SEQ * SEQ];

// ---------------------------------------------------------------------------
// Helpers
// ---------------------------------------------------------------------------
__device__ __forceinline__ uint32_t smem_u32(const void* p) {
    uint32_t a;
    asm("{ .reg .u64 t; cvta.to.shared.u64 t, %1; cvt.u32.u64 %0, t; }" : "=r"(a) : "l"(p));
    return a;
}
#define SW128(x) ((uint32_t)(x) ^ ((((uint32_t)(x)) >> 3) & 0x70))

__device__ __forceinline__ void ldmx4(uint32_t* r, uint32_t addr) {
    asm volatile("ldmatrix.sync.aligned.m8n8.x4.shared.b16 {%0,%1,%2,%3}, [%4];"
                 : "=r"(r[0]), "=r"(r[1]), "=r"(r[2]), "=r"(r[3]) : "r"(addr));
}
__device__ __forceinline__ void mma16816bf(float* c, const uint32_t* a, const uint32_t* b) {
    asm volatile("mma.sync.aligned.m16n8k16.row.col.f32.bf16.bf16.f32 "
                 "{%0,%1,%2,%3}, {%4,%5,%6,%7}, {%8,%9}, {%0,%1,%2,%3};"
                 : "+f"(c[0]), "+f"(c[1]), "+f"(c[2]), "+f"(c[3])
                 : "r"(a[0]), "r"(a[1]), "r"(a[2]), "r"(a[3]), "r"(b[0]), "r"(b[1]));
}
__device__ __forceinline__ void mma16816h(float* c, const uint32_t* a, const uint32_t* b) {
    asm volatile("mma.sync.aligned.m16n8k16.row.col.f32.f16.f16.f32 "
                 "{%0,%1,%2,%3}, {%4,%5,%6,%7}, {%8,%9}, {%0,%1,%2,%3};"
                 : "+f"(c[0]), "+f"(c[1]), "+f"(c[2]), "+f"(c[3])
                 : "r"(a[0]), "r"(a[1]), "r"(a[2]), "r"(a[3]), "r"(b[0]), "r"(b[1]));
}

// fp32 -> bf16 hi/lo split of 8 consecutive floats (qk path)
__device__ __forceinline__ void split8(const float* p, uint4& hi, uint4& lo) {
    float4 a = *(const float4*)p;
    float4 b = *(const float4*)(p + 4);
    float x[8] = {a.x, a.y, a.z, a.w, b.x, b.y, b.z, b.w};
    __nv_bfloat162* hp = (__nv_bfloat162*)&hi;
    __nv_bfloat162* lp = (__nv_bfloat162*)&lo;
#pragma unroll
    for (int i = 0; i < 4; i++) {
        __nv_bfloat16 h0 = __float2bfloat16(x[2*i]);
        __nv_bfloat16 h1 = __float2bfloat16(x[2*i+1]);
        float r0 = x[2*i]   - __bfloat162float(h0);
        float r1 = x[2*i+1] - __bfloat162float(h1);
        hp[i] = __halves2bfloat162(h0, h1);
        lp[i] = __floats2bfloat162_rn(r0, r1);
    }
}

// ---------------------------------------------------------------------------
// Kernel 0: V transpose + fp16 convert  v[bh][k][d] -> vT[bh][d][k]
// ---------------------------------------------------------------------------
__global__ __launch_bounds__(256) void vsplit_kernel(const float* __restrict__ v) {
    __shared__ float s[32][33];
    int k0 = blockIdx.x * 32, d0 = blockIdx.y * 32, bh = blockIdx.z;
    const float* vb = v + (size_t)bh * SEQ * DIM;
    int t = threadIdx.x;
#pragma unroll
    for (int i = 0; i < 4; i++) {
        int e = t + i * 256;
        int kk = e >> 5, dd = e & 31;
        s[kk][dd] = vb[(size_t)(k0 + kk) * DIM + d0 + dd];
    }
    __syncthreads();
#pragma unroll
    for (int i = 0; i < 4; i++) {
        int e = t + i * 256;
        int dd = e >> 5, kk = e & 31;
        size_t o = ((size_t)bh * DIM + d0 + dd) * SEQ + k0 + kk;
        g_vT_f16[o] = __float2half(s[kk][dd]);
    }
}

// ---------------------------------------------------------------------------
// Kernel 1: scores = (Q . K^T)/8 via mma.sync bf16 hi/lo split.
// Now stores fp16 scores to g_scores (halved store stream).
// ---------------------------------------------------------------------------
#define QK_QHI 0u
#define QK_QLO 16384u
#define QK_KHI 32768u
#define QK_KLO 49152u
#define QK_SMEM 65536

__global__ __launch_bounds__(256) void qk_mma_kernel(
    const float* __restrict__ q, const float* __restrict__ k)
{
    extern __shared__ char smem[];
    uint32_t sbase = smem_u32(smem);
    const int tid = threadIdx.x;
    const int wid = tid >> 5;
    const int lane = tid & 31;
    const int wr = wid >> 2;
    const int wc = wid & 3;

    const int bh = blockIdx.z;
    const int q0 = blockIdx.y * 128;
    const int k0 = blockIdx.x * 128;
    const float* qb = q + ((size_t)bh * SEQ + q0) * DIM;
    const float* kb = k + ((size_t)bh * SEQ + k0) * DIM;

    for (int t = tid; t < 1024; t += 256) {
        int row = t >> 3, c0 = (t & 7) << 3;
        uint32_t off = SW128(row * 128 + c0 * 2);
        uint4 hi, lo;
        split8(qb + (size_t)row * DIM + c0, hi, lo);
        *(uint4*)(smem + QK_QHI + off) = hi;
        *(uint4*)(smem + QK_QLO + off) = lo;
        split8(kb + (size_t)row * DIM + c0, hi, lo);
        *(uint4*)(smem + QK_KHI + off) = hi;
        *(uint4*)(smem + QK_KLO + off) = lo;
    }
    __syncthreads();

    float acc[4][4][4];
#pragma unroll
    for (int m = 0; m < 4; m++)
#pragma unroll
        for (int n = 0; n < 4; n++)
#pragma unroll
            for (int i = 0; i < 4; i++) acc[m][n][i] = 0.0f;

    const int a_row = wr * 64 + (lane & 15);
    const int a_cb  = (lane >> 4) << 4;
    const int b_row = wc * 32 + ((lane >> 4) << 3) + (lane & 7);
    const int b_cb  = ((lane >> 3) & 1) << 4;

#pragma unroll
    for (int kc = 0; kc < 4; kc++) {
        const int kb16 = kc * 32;
        uint32_t Ahi[4][4], Alo[4][4];
#pragma unroll
        for (int m = 0; m < 4; m++) {
            uint32_t off = SW128((a_row + m * 16) * 128 + kb16 + a_cb);
            ldmx4(Ahi[m], sbase + QK_QHI + off);
            ldmx4(Alo[m], sbase + QK_QLO + off);
        }
        uint32_t Bhi[2][4], Blo[2][4];
#pragma unroll
        for (int p = 0; p < 2; p++) {
            uint32_t off = SW128((b_row + p * 16) * 128 + kb16 + b_cb);
            ldmx4(Bhi[p], sbase + QK_KHI + off);
            ldmx4(Blo[p], sbase + QK_KLO + off);
        }
#pragma unroll
        for (int m = 0; m < 4; m++)
#pragma unroll
            for (int n = 0; n < 4; n++) {
                const uint32_t* bh2 = &Bhi[n >> 1][(n & 1) * 2];
                const uint32_t* bl2 = &Blo[n >> 1][(n & 1) * 2];
                mma16816bf(acc[m][n], Ahi[m], bh2);
                mma16816bf(acc[m][n], Ahi[m], bl2);
                mma16816bf(acc[m][n], Alo[m], bh2);
            }
    }

    __half* sc = g_scores + ((size_t)bh * SEQ + q0) * SEQ + k0;
    const int er = (lane >> 2);
    const int ec = (lane & 3) * 2;
#pragma unroll
    for (int m = 0; m < 4; m++) {
        int row = wr * 64 + m * 16 + er;
#pragma unroll
        for (int n = 0; n < 4; n++) {
            int col = wc * 32 + n * 8 + ec;
            *(__half2*)(sc + (size_t)row * SEQ + col) =
                __floats2half2_rn(acc[m][n][0] * 0.125f, acc[m][n][1] * 0.125f);
            *(__half2*)(sc + (size_t)(row + 8) * SEQ + col) =
                __floats2half2_rn(acc[m][n][2] * 0.125f, acc[m][n][3] * 0.125f);
        }
    }
}

// ---------------------------------------------------------------------------
// Kernel 2 (FUSED softmax + AV, R9 structure): CTA = (b, 32 q, all 16 heads),
// 512 threads = 16 warps, warp w owns head w's MMA.
// Per 32-k chunk: read fp16 scores (g_scores), softmax over heads in regs,
// write fp32 attn (output) + fp16 A planes (smem); stage V; MMA.
// smem: V planes 16 x 64 x 80B = 80KB, A planes 16 x 32 x 80B = 40KB.
// ---------------------------------------------------------------------------
#define FK 32
#define VP_ROW 80
#define VP_STRIDE (64*VP_ROW)
#define AP_BASE  (16*VP_STRIDE)
#define AP_ROW 80
#define AP_STRIDE (32*AP_ROW)
#define FAV_SMEM (AP_BASE + 16*AP_STRIDE)  // 122880

__global__ __launch_bounds__(512) void softmax_av_fused_kernel(
    float* __restrict__ attn, float* __restrict__ out)
{
    extern __shared__ char smem[];
    uint32_t sbase = smem_u32(smem);
    const int tid = threadIdx.x;
    const int wid = tid >> 5;          // head
    const int lane = tid & 31;
    const int b  = blockIdx.y;
    const int q0 = blockIdx.x * 32;

    const int sq = tid >> 4;           // 0..31
    const int sk = (lane & 15) * 2;    // 0,2,..,30

    const size_t plane = (size_t)SEQ * SEQ;
    const __half* vt = g_vT_f16 + (size_t)(b * HH + wid) * DIM * SEQ;
    const __half* sc = g_scores + (size_t)b * HH * plane;
    float* ab = attn + (size_t)b * HH * plane;

    float acc[2][8][4];
#pragma unroll
    for (int m = 0; m < 2; m++)
#pragma unroll
        for (int n = 0; n < 8; n++)
#pragma unroll
            for (int i = 0; i < 4; i++) acc[m][n][i] = 0.0f;

    const int a_row = lane & 15;
    const int a_cb  = (lane >> 4) << 4;
    const int b_row = ((lane >> 4) << 3) + (lane & 7);
    const int b_cb  = ((lane >> 3) & 1) << 4;
    const uint32_t Vp = sbase + wid * VP_STRIDE;
    const uint32_t Ap = sbase + AP_BASE + wid * AP_STRIDE;

    for (int ic = 0; ic < SEQ / FK; ic++) {
        const int kc0 = ic * FK;

        // --- stage this head's V chunk: 64 rows x 32 halves (4KB)
#pragma unroll
        for (int i = 0; i < 8; i++) {
            int idx = i * 32 + lane;
            int d = idx >> 2, j = idx & 3;
            uint4 v = *(const uint4*)(vt + (size_t)d * SEQ + kc0 + j * 8);
            *(uint4*)(smem + wid * VP_STRIDE + d * VP_ROW + j * 16) = v;
        }

        // --- softmax over heads for this thread's 2 positions (fp16 scores)
        {
            float ex[HH][2];
            float s0 = 0.0f, s1 = 0.0f;
            const size_t base = (size_t)(q0 + sq) * SEQ + kc0 + sk;
#pragma unroll
            for (int hh = 0; hh < HH; hh++) {
                float2 v = __half22float2(*(const __half2*)(sc + (size_t)hh * plane + base));
                ex[hh][0] = __expf(v.x);
                ex[hh][1] = __expf(v.y);
                s0 += ex[hh][0];
                s1 += ex[hh][1];
            }
            const float i0 = 1.0f / s0, i1 = 1.0f / s1;
#pragma unroll
            for (int hh = 0; hh < HH; hh++) {
                float a0 = ex[hh][0] * i0;
                float a1 = ex[hh][1] * i1;
                *(__half2*)(smem + AP_BASE + hh * AP_STRIDE + sq * AP_ROW + sk * 2) =
                    __floats2half2_rn(a0, a1);
                float2 w = { a0, a1 };
                *(float2*)(ab + (size_t)hh * plane + base) = w;
            }
        }
        __syncthreads();

        // --- MMA for this warp's head: A 32x32 @ V^T 64x32 -> 32x64
#pragma unroll
        for (int kc = 0; kc < 2; kc++) {
            uint32_t Ah[2][4];
#pragma unroll
            for (int m = 0; m < 2; m++)
                ldmx4(Ah[m], Ap + (m * 16 + a_row) * AP_ROW + kc * 32 + a_cb);
            uint32_t Bh[4][4];
#pragma unroll
            for (int p = 0; p < 4; p++)
                ldmx4(Bh[p], Vp + (p * 16 + b_row) * VP_ROW + kc * 32 + b_cb);
#pragma unroll
            for (int m = 0; m < 2; m++)
#pragma unroll
                for (int n = 0; n < 8; n++)
                    mma16816h(acc[m][n], Ah[m], &Bh[n >> 1][(n & 1) * 2]);
        }
        __syncthreads();
    }

    // --- epilogue: warp writes its head's out block (32q x 64d)
    float* ob = out + ((size_t)(b * HH + wid) * SEQ + q0) * DIM;
    const int er = lane >> 2;
    const int ec = (lane & 3) * 2;
#pragma unroll
    for (int m = 0; m < 2; m++) {
        int row = m * 16 + er;
#pragma unroll
        for (int n = 0; n < 8; n++) {
            int col = n * 8 + ec;
            float2 v0 = { acc[m][n][0], acc[m][n][1] };
            float2 v1 = { acc[m][n][2], acc[m][n][3] };
            *(float2*)(ob + (size_t)row * DIM + col) = v0;
            *(float2*)(ob + (size_t)(row + 8) * DIM + col) = v1;
        }
    }
}

// ---------------------------------------------------------------------------
// Launch: d_out = [ out (B*H*S*D) | attn (B*H*S*S) ]
// ---------------------------------------------------------------------------
extern "C" void kernel_launch(void* const* d_in, const int* in_sizes, int n_in,
                              void* d_out, int out_size)
{
    const float* q = (const float*)d_in[0];
    const float* k = (const float*)d_in[1];
    const float* v = (const float*)d_in[2];

    float* out  = (float*)d_out;
    float* attn = out + (size_t)BB * HH * SEQ * DIM;

    cudaFuncSetAttribute(qk_mma_kernel,
                         cudaFuncAttributeMaxDynamicSharedMemorySize, QK_SMEM);
    cudaFuncSetAttribute(softmax_av_fused_kernel,
                         cudaFuncAttributeMaxDynamicSharedMemorySize, FAV_SMEM);

    // 0) V transpose + fp16 convert
    {
        dim3 grid(SEQ / 32, DIM / 32, BH);
        vsplit_kernel<<<grid, 256>>>(v);
    }
    // 1) raw scores (fp16) -> g_scores scratch
    {
        dim3 grid(SEQ / 128, SEQ / 128, BH);
        qk_mma_kernel<<<grid, 256, QK_SMEM>>>(q, k);
    }
    // 2) fused: softmax over heads (fp16 scores -> fp32 attn) + out = attn @ V
    {
        dim3 grid(SEQ / 32, BB);
        softmax_av_fused_kernel<<<grid, 512, FAV_SMEM>>>(attn, out);
    }
}

// round 16
// speedup vs baseline: 1.1731x; 1.1731x over previous
#include <cuda_runtime.h>
#include <cuda_bf16.h>
#include <cuda_fp16.h>
#include <cstdint>

// Problem constants: B=2, H=16, S=2048, D=64
#define BB 2
#define HH 16
#define SEQ 2048
#define DIM 64
#define BH (BB*HH)

// Scratch: V transposed fp16 (8.4 MB) + raw scores fp16 (268 MB)
__device__ __half g_vT_f16[(size_t)BH * DIM * SEQ];
__device__ __half g_scores[(size_t)BH * SEQ * SEQ];

// ---------------------------------------------------------------------------
// Helpers
// ---------------------------------------------------------------------------
__device__ __forceinline__ uint32_t smem_u32(const void* p) {
    uint32_t a;
    asm("{ .reg .u64 t; cvta.to.shared.u64 t, %1; cvt.u32.u64 %0, t; }" : "=r"(a) : "l"(p));
    return a;
}
#define SW128(x) ((uint32_t)(x) ^ ((((uint32_t)(x)) >> 3) & 0x70))
// swizzle for 64-byte rows (validated R11)
#define SW64X(x) ((uint32_t)(x) ^ ((((uint32_t)(x)) >> 3) & 0x30))

__device__ __forceinline__ void ldmx4(uint32_t* r, uint32_t addr) {
    asm volatile("ldmatrix.sync.aligned.m8n8.x4.shared.b16 {%0,%1,%2,%3}, [%4];"
                 : "=r"(r[0]), "=r"(r[1]), "=r"(r[2]), "=r"(r[3]) : "r"(addr));
}
__device__ __forceinline__ void mma16816bf(float* c, const uint32_t* a, const uint32_t* b) {
    asm volatile("mma.sync.aligned.m16n8k16.row.col.f32.bf16.bf16.f32 "
                 "{%0,%1,%2,%3}, {%4,%5,%6,%7}, {%8,%9}, {%0,%1,%2,%3};"
                 : "+f"(c[0]), "+f"(c[1]), "+f"(c[2]), "+f"(c[3])
                 : "r"(a[0]), "r"(a[1]), "r"(a[2]), "r"(a[3]), "r"(b[0]), "r"(b[1]));
}
__device__ __forceinline__ void mma16816h(float* c, const uint32_t* a, const uint32_t* b) {
    asm volatile("mma.sync.aligned.m16n8k16.row.col.f32.f16.f16.f32 "
                 "{%0,%1,%2,%3}, {%4,%5,%6,%7}, {%8,%9}, {%0,%1,%2,%3};"
                 : "+f"(c[0]), "+f"(c[1]), "+f"(c[2]), "+f"(c[3])
                 : "r"(a[0]), "r"(a[1]), "r"(a[2]), "r"(a[3]), "r"(b[0]), "r"(b[1]));
}

// fp32 -> bf16 hi/lo split of 8 consecutive floats (qk path)
__device__ __forceinline__ void split8(const float* p, uint4& hi, uint4& lo) {
    float4 a = *(const float4*)p;
    float4 b = *(const float4*)(p + 4);
    float x[8] = {a.x, a.y, a.z, a.w, b.x, b.y, b.z, b.w};
    __nv_bfloat162* hp = (__nv_bfloat162*)&hi;
    __nv_bfloat162* lp = (__nv_bfloat162*)&lo;
#pragma unroll
    for (int i = 0; i < 4; i++) {
        __nv_bfloat16 h0 = __float2bfloat16(x[2*i]);
        __nv_bfloat16 h1 = __float2bfloat16(x[2*i+1]);
        float r0 = x[2*i]   - __bfloat162float(h0);
        float r1 = x[2*i+1] - __bfloat162float(h1);
        hp[i] = __halves2bfloat162(h0, h1);
        lp[i] = __floats2bfloat162_rn(r0, r1);
    }
}

// ---------------------------------------------------------------------------
// Kernel 0: V transpose + fp16 convert  v[bh][k][d] -> vT[bh][d][k]
// ---------------------------------------------------------------------------
__global__ __launch_bounds__(256) void vsplit_kernel(const float* __restrict__ v) {
    __shared__ float s[32][33];
    int k0 = blockIdx.x * 32, d0 = blockIdx.y * 32, bh = blockIdx.z;
    const float* vb = v + (size_t)bh * SEQ * DIM;
    int t = threadIdx.x;
#pragma unroll
    for (int i = 0; i < 4; i++) {
        int e = t + i * 256;
        int kk = e >> 5, dd = e & 31;
        s[kk][dd] = vb[(size_t)(k0 + kk) * DIM + d0 + dd];
    }
    __syncthreads();
#pragma unroll
    for (int i = 0; i < 4; i++) {
        int e = t + i * 256;
        int dd = e >> 5, kk = e & 31;
        size_t o = ((size_t)bh * DIM + d0 + dd) * SEQ + k0 + kk;
        g_vT_f16[o] = __float2half(s[kk][dd]);
    }
}

// ---------------------------------------------------------------------------
// Kernel 1: scores = (Q . K^T)/8, bf16 hi/lo split MMA; fp16 scores out via
// smem-bounce epilogue (full-sector coalesced stores).
// Bounce tile: 128 rows x 272B pitch = 34,816B (fits the 64KB staging smem).
// ---------------------------------------------------------------------------
#define QK_QHI 0u
#define QK_QLO 16384u
#define QK_KHI 32768u
#define QK_KLO 49152u
#define QK_SMEM 65536
#define EP_PITCH 272

__global__ __launch_bounds__(256) void qk_mma_kernel(
    const float* __restrict__ q, const float* __restrict__ k)
{
    extern __shared__ char smem[];
    uint32_t sbase = smem_u32(smem);
    const int tid = threadIdx.x;
    const int wid = tid >> 5;
    const int lane = tid & 31;
    const int wr = wid >> 2;
    const int wc = wid & 3;

    const int bh = blockIdx.z;
    const int q0 = blockIdx.y * 128;
    const int k0 = blockIdx.x * 128;
    const float* qb = q + ((size_t)bh * SEQ + q0) * DIM;
    const float* kb = k + ((size_t)bh * SEQ + k0) * DIM;

    for (int t = tid; t < 1024; t += 256) {
        int row = t >> 3, c0 = (t & 7) << 3;
        uint32_t off = SW128(row * 128 + c0 * 2);
        uint4 hi, lo;
        split8(qb + (size_t)row * DIM + c0, hi, lo);
        *(uint4*)(smem + QK_QHI + off) = hi;
        *(uint4*)(smem + QK_QLO + off) = lo;
        split8(kb + (size_t)row * DIM + c0, hi, lo);
        *(uint4*)(smem + QK_KHI + off) = hi;
        *(uint4*)(smem + QK_KLO + off) = lo;
    }
    __syncthreads();

    float acc[4][4][4];
#pragma unroll
    for (int m = 0; m < 4; m++)
#pragma unroll
        for (int n = 0; n < 4; n++)
#pragma unroll
            for (int i = 0; i < 4; i++) acc[m][n][i] = 0.0f;

    const int a_row = wr * 64 + (lane & 15);
    const int a_cb  = (lane >> 4) << 4;
    const int b_row = wc * 32 + ((lane >> 4) << 3) + (lane & 7);
    const int b_cb  = ((lane >> 3) & 1) << 4;

#pragma unroll
    for (int kc = 0; kc < 4; kc++) {
        const int kb16 = kc * 32;
        uint32_t Ahi[4][4], Alo[4][4];
#pragma unroll
        for (int m = 0; m < 4; m++) {
            uint32_t off = SW128((a_row + m * 16) * 128 + kb16 + a_cb);
            ldmx4(Ahi[m], sbase + QK_QHI + off);
            ldmx4(Alo[m], sbase + QK_QLO + off);
        }
        uint32_t Bhi[2][4], Blo[2][4];
#pragma unroll
        for (int p = 0; p < 2; p++) {
            uint32_t off = SW128((b_row + p * 16) * 128 + kb16 + b_cb);
            ldmx4(Bhi[p], sbase + QK_KHI + off);
            ldmx4(Blo[p], sbase + QK_KLO + off);
        }
#pragma unroll
        for (int m = 0; m < 4; m++)
#pragma unroll
            for (int n = 0; n < 4; n++) {
                const uint32_t* bh2 = &Bhi[n >> 1][(n & 1) * 2];
                const uint32_t* bl2 = &Blo[n >> 1][(n & 1) * 2];
                mma16816bf(acc[m][n], Ahi[m], bh2);
                mma16816bf(acc[m][n], Ahi[m], bl2);
                mma16816bf(acc[m][n], Alo[m], bh2);
            }
    }

    // ---- epilogue: STS fp16 tile (pitch 272B), then coalesced uint4 STG
    __syncthreads();   // staging smem reuse
    {
        const int er = (lane >> 2);
        const int ec = (lane & 3) * 2;
#pragma unroll
        for (int m = 0; m < 4; m++) {
            int row = wr * 64 + m * 16 + er;
#pragma unroll
            for (int n = 0; n < 4; n++) {
                int col = wc * 32 + n * 8 + ec;
                *(__half2*)(smem + row * EP_PITCH + col * 2) =
                    __floats2half2_rn(acc[m][n][0] * 0.125f, acc[m][n][1] * 0.125f);
                *(__half2*)(smem + (row + 8) * EP_PITCH + col * 2) =
                    __floats2half2_rn(acc[m][n][2] * 0.125f, acc[m][n][3] * 0.125f);
            }
        }
    }
    __syncthreads();
    {
        __half* sc = g_scores + ((size_t)bh * SEQ + q0) * SEQ + k0;
        const int r = tid >> 1;          // 0..127
        const int hf = tid & 1;          // 0..1 (half-row, 64 halves each)
#pragma unroll
        for (int i = 0; i < 8; i++) {
            uint4 v = *(uint4*)(smem + r * EP_PITCH + hf * 128 + i * 16);
            *(uint4*)(sc + (size_t)r * SEQ + hf * 64 + i * 8) = v;
        }
    }
}

// ---------------------------------------------------------------------------
// Kernel 2 (FUSED softmax + AV): CTA = (b, 32 q, all 16 heads),
// 512 threads = 16 warps, warp w = head w. R9 serial structure.
// Reads fp16 scores (g_scores), softmaxes over heads in regs,
// writes fp32 attn (output) + fp16 A planes (smem); stages V; MMA.
// smem (SW64X, 64B rows): V planes 16 x 64 x 64B = 64KB, A planes
// 16 x 32 x 64B = 32KB. Total 96KB.
// ---------------------------------------------------------------------------
#define FK 32
#define FV_STRIDE 4096u
#define FA_BASE   65536u
#define FA_STRIDE 2048u
#define FAV_SMEM  98304

__global__ __launch_bounds__(512) void softmax_av_fused_kernel(
    float* __restrict__ attn, float* __restrict__ out)
{
    extern __shared__ char smem[];
    uint32_t sbase = smem_u32(smem);
    const int tid = threadIdx.x;
    const int wid = tid >> 5;          // head
    const int lane = tid & 31;
    const int b  = blockIdx.y;
    const int q0 = blockIdx.x * 32;

    const int sq = tid >> 4;           // 0..31
    const int sk = (lane & 15) * 2;    // 0,2,..,30

    const size_t plane = (size_t)SEQ * SEQ;
    const __half* vt = g_vT_f16 + (size_t)(b * HH + wid) * DIM * SEQ;
    const __half* sc = g_scores + (size_t)b * HH * plane;
    float* ab = attn + (size_t)b * HH * plane;

    float acc[2][8][4];
#pragma unroll
    for (int m = 0; m < 2; m++)
#pragma unroll
        for (int n = 0; n < 8; n++)
#pragma unroll
            for (int i = 0; i < 4; i++) acc[m][n][i] = 0.0f;

    const int a_row = lane & 15;
    const int a_cb  = (lane >> 4) << 4;
    const int b_row = ((lane >> 4) << 3) + (lane & 7);
    const int b_cb  = ((lane >> 3) & 1) << 4;
    const uint32_t Vp = sbase + wid * FV_STRIDE;
    const uint32_t Ap = sbase + FA_BASE + wid * FA_STRIDE;
    const uint32_t aoff = SW64X((uint32_t)(sq * 64 + sk * 2));

    for (int ic = 0; ic < SEQ / FK; ic++) {
        const int kc0 = ic * FK;

        // --- stage this head's V chunk: 64 rows(d) x 32 halves (4KB, SW64X)
#pragma unroll
        for (int i = 0; i < 8; i++) {
            int idx = i * 32 + lane;
            int d = idx >> 2, j = idx & 3;
            uint4 v = *(const uint4*)(vt + (size_t)d * SEQ + kc0 + j * 8);
            *(uint4*)(smem + wid * FV_STRIDE + SW64X(d * 64 + j * 16)) = v;
        }

        // --- softmax over heads for this thread's 2 positions (fp16 scores)
        {
            float ex[HH][2];
            float s0 = 0.0f, s1 = 0.0f;
            const size_t base = (size_t)(q0 + sq) * SEQ + kc0 + sk;
#pragma unroll
            for (int hh = 0; hh < HH; hh++) {
                float2 v = __half22float2(*(const __half2*)(sc + (size_t)hh * plane + base));
                ex[hh][0] = __expf(v.x);
                ex[hh][1] = __expf(v.y);
                s0 += ex[hh][0];
                s1 += ex[hh][1];
            }
            const float i0 = 1.0f / s0, i1 = 1.0f / s1;
#pragma unroll
            for (int hh = 0; hh < HH; hh++) {
                float a0 = ex[hh][0] * i0;
                float a1 = ex[hh][1] * i1;
                *(__half2*)(smem + FA_BASE + hh * FA_STRIDE + aoff) =
                    __floats2half2_rn(a0, a1);
                float2 w = { a0, a1 };
                *(float2*)(ab + (size_t)hh * plane + base) = w;
            }
        }
        __syncthreads();

        // --- MMA for this warp's head: A 32x32 @ V^T 64x32 -> 32x64
#pragma unroll
        for (int kc = 0; kc < 2; kc++) {
            uint32_t Ah[2][4];
#pragma unroll
            for (int m = 0; m < 2; m++)
                ldmx4(Ah[m], Ap + SW64X((m * 16 + a_row) * 64 + kc * 32 + a_cb));
            uint32_t Bh[4][4];
#pragma unroll
            for (int p = 0; p < 4; p++)
                ldmx4(Bh[p], Vp + SW64X((p * 16 + b_row) * 64 + kc * 32 + b_cb));
#pragma unroll
            for (int m = 0; m < 2; m++)
#pragma unroll
                for (int n = 0; n < 8; n++)
                    mma16816h(acc[m][n], Ah[m], &Bh[n >> 1][(n & 1) * 2]);
        }
        __syncthreads();
    }

    // --- epilogue: warp writes its head's out block (32q x 64d)
    float* ob = out + ((size_t)(b * HH + wid) * SEQ + q0) * DIM;
    const int er = lane >> 2;
    const int ec = (lane & 3) * 2;
#pragma unroll
    for (int m = 0; m < 2; m++) {
        int row = m * 16 + er;
#pragma unroll
        for (int n = 0; n < 8; n++) {
            int col = n * 8 + ec;
            float2 v0 = { acc[m][n][0], acc[m][n][1] };
            float2 v1 = { acc[m][n][2], acc[m][n][3] };
            *(float2*)(ob + (size_t)row * DIM + col) = v0;
            *(float2*)(ob + (size_t)(row + 8) * DIM + col) = v1;
        }
    }
}

// ---------------------------------------------------------------------------
// Launch: d_out = [ out (B*H*S*D) | attn (B*H*S*S) ]
// ---------------------------------------------------------------------------
extern "C" void kernel_launch(void* const* d_in, const int* in_sizes, int n_in,
                              void* d_out, int out_size)
{
    const float* q = (const float*)d_in[0];
    const float* k = (const float*)d_in[1];
    const float* v = (const float*)d_in[2];

    float* out  = (float*)d_out;
    float* attn = out + (size_t)BB * HH * SEQ * DIM;

    cudaFuncSetAttribute(qk_mma_kernel,
                         cudaFuncAttributeMaxDynamicSharedMemorySize, QK_SMEM);
    cudaFuncSetAttribute(softmax_av_fused_kernel,
                         cudaFuncAttributeMaxDynamicSharedMemorySize, FAV_SMEM);

    // 0) V transpose + fp16 convert
    {
        dim3 grid(SEQ / 32, DIM / 32, BH);
        vsplit_kernel<<<grid, 256>>>(v);
    }
    // 1) raw scores (fp16, coalesced) -> g_scores scratch
    {
        dim3 grid(SEQ / 128, SEQ / 128, BH);
        qk_mma_kernel<<<grid, 256, QK_SMEM>>>(q, k);
    }
    // 2) fused: softmax over heads (fp16 scores -> fp32 attn) + out = attn @ V
    {
        dim3 grid(SEQ / 32, BB);
        softmax_av_fused_kernel<<<grid, 512, FAV_SMEM>>>(attn, out);
    }
}

// round 17
// speedup vs baseline: 1.2145x; 1.0352x over previous
#include <cuda_runtime.h>
#include <cuda_bf16.h>
#include <cuda_fp16.h>
#include <cstdint>

// Problem constants: B=2, H=16, S=2048, D=64
#define BB 2
#define HH 16
#define SEQ 2048
#define DIM 64
#define BH (BB*HH)

// Scratch: V transposed fp16 (8.4 MB) + raw scores fp16 (268 MB)
__device__ __half g_vT_f16[(size_t)BH * DIM * SEQ];
__device__ __half g_scores[(size_t)BH * SEQ * SEQ];

// ---------------------------------------------------------------------------
// Helpers
// ---------------------------------------------------------------------------
__device__ __forceinline__ uint32_t smem_u32(const void* p) {
    uint32_t a;
    asm("{ .reg .u64 t; cvta.to.shared.u64 t, %1; cvt.u32.u64 %0, t; }" : "=r"(a) : "l"(p));
    return a;
}
#define SW128(x) ((uint32_t)(x) ^ ((((uint32_t)(x)) >> 3) & 0x70))
// swizzle for 64-byte rows (validated R11)
#define SW64X(x) ((uint32_t)(x) ^ ((((uint32_t)(x)) >> 3) & 0x30))

__device__ __forceinline__ void ldmx4(uint32_t* r, uint32_t addr) {
    asm volatile("ldmatrix.sync.aligned.m8n8.x4.shared.b16 {%0,%1,%2,%3}, [%4];"
                 : "=r"(r[0]), "=r"(r[1]), "=r"(r[2]), "=r"(r[3]) : "r"(addr));
}
__device__ __forceinline__ void mma16816bf(float* c, const uint32_t* a, const uint32_t* b) {
    asm volatile("mma.sync.aligned.m16n8k16.row.col.f32.bf16.bf16.f32 "
                 "{%0,%1,%2,%3}, {%4,%5,%6,%7}, {%8,%9}, {%0,%1,%2,%3};"
                 : "+f"(c[0]), "+f"(c[1]), "+f"(c[2]), "+f"(c[3])
                 : "r"(a[0]), "r"(a[1]), "r"(a[2]), "r"(a[3]), "r"(b[0]), "r"(b[1]));
}
__device__ __forceinline__ void mma16816h(float* c, const uint32_t* a, const uint32_t* b) {
    asm volatile("mma.sync.aligned.m16n8k16.row.col.f32.f16.f16.f32 "
                 "{%0,%1,%2,%3}, {%4,%5,%6,%7}, {%8,%9}, {%0,%1,%2,%3};"
                 : "+f"(c[0]), "+f"(c[1]), "+f"(c[2]), "+f"(c[3])
                 : "r"(a[0]), "r"(a[1]), "r"(a[2]), "r"(a[3]), "r"(b[0]), "r"(b[1]));
}

// fp32 -> bf16 hi/lo split of 8 consecutive floats (qk path)
__device__ __forceinline__ void split8(const float* p, uint4& hi, uint4& lo) {
    float4 a = *(const float4*)p;
    float4 b = *(const float4*)(p + 4);
    float x[8] = {a.x, a.y, a.z, a.w, b.x, b.y, b.z, b.w};
    __nv_bfloat162* hp = (__nv_bfloat162*)&hi;
    __nv_bfloat162* lp = (__nv_bfloat162*)&lo;
#pragma unroll
    for (int i = 0; i < 4; i++) {
        __nv_bfloat16 h0 = __float2bfloat16(x[2*i]);
        __nv_bfloat16 h1 = __float2bfloat16(x[2*i+1]);
        float r0 = x[2*i]   - __bfloat162float(h0);
        float r1 = x[2*i+1] - __bfloat162float(h1);
        hp[i] = __halves2bfloat162(h0, h1);
        lp[i] = __floats2bfloat162_rn(r0, r1);
    }
}

// ---------------------------------------------------------------------------
// Kernel 0: V transpose + fp16 convert  v[bh][k][d] -> vT[bh][d][k]
// ---------------------------------------------------------------------------
__global__ __launch_bounds__(256) void vsplit_kernel(const float* __restrict__ v) {
    __shared__ float s[32][33];
    int k0 = blockIdx.x * 32, d0 = blockIdx.y * 32, bh = blockIdx.z;
    const float* vb = v + (size_t)bh * SEQ * DIM;
    int t = threadIdx.x;
#pragma unroll
    for (int i = 0; i < 4; i++) {
        int e = t + i * 256;
        int kk = e >> 5, dd = e & 31;
        s[kk][dd] = vb[(size_t)(k0 + kk) * DIM + d0 + dd];
    }
    __syncthreads();
#pragma unroll
    for (int i = 0; i < 4; i++) {
        int e = t + i * 256;
        int dd = e >> 5, kk = e & 31;
        size_t o = ((size_t)bh * DIM + d0 + dd) * SEQ + k0 + kk;
        g_vT_f16[o] = __float2half(s[kk][dd]);
    }
}

// ---------------------------------------------------------------------------
// Kernel 1: scores = (Q . K^T)/8, bf16 hi/lo split MMA; fp16 scores out via
// smem-bounce epilogue (full-sector coalesced stores). (R16, unchanged)
// ---------------------------------------------------------------------------
#define QK_QHI 0u
#define QK_QLO 16384u
#define QK_KHI 32768u
#define QK_KLO 49152u
#define QK_SMEM 65536
#define EP_PITCH 272

__global__ __launch_bounds__(256) void qk_mma_kernel(
    const float* __restrict__ q, const float* __restrict__ k)
{
    extern __shared__ char smem[];
    uint32_t sbase = smem_u32(smem);
    const int tid = threadIdx.x;
    const int wid = tid >> 5;
    const int lane = tid & 31;
    const int wr = wid >> 2;
    const int wc = wid & 3;

    const int bh = blockIdx.z;
    const int q0 = blockIdx.y * 128;
    const int k0 = blockIdx.x * 128;
    const float* qb = q + ((size_t)bh * SEQ + q0) * DIM;
    const float* kb = k + ((size_t)bh * SEQ + k0) * DIM;

    for (int t = tid; t < 1024; t += 256) {
        int row = t >> 3, c0 = (t & 7) << 3;
        uint32_t off = SW128(row * 128 + c0 * 2);
        uint4 hi, lo;
        split8(qb + (size_t)row * DIM + c0, hi, lo);
        *(uint4*)(smem + QK_QHI + off) = hi;
        *(uint4*)(smem + QK_QLO + off) = lo;
        split8(kb + (size_t)row * DIM + c0, hi, lo);
        *(uint4*)(smem + QK_KHI + off) = hi;
        *(uint4*)(smem + QK_KLO + off) = lo;
    }
    __syncthreads();

    float acc[4][4][4];
#pragma unroll
    for (int m = 0; m < 4; m++)
#pragma unroll
        for (int n = 0; n < 4; n++)
#pragma unroll
            for (int i = 0; i < 4; i++) acc[m][n][i] = 0.0f;

    const int a_row = wr * 64 + (lane & 15);
    const int a_cb  = (lane >> 4) << 4;
    const int b_row = wc * 32 + ((lane >> 4) << 3) + (lane & 7);
    const int b_cb  = ((lane >> 3) & 1) << 4;

#pragma unroll
    for (int kc = 0; kc < 4; kc++) {
        const int kb16 = kc * 32;
        uint32_t Ahi[4][4], Alo[4][4];
#pragma unroll
        for (int m = 0; m < 4; m++) {
            uint32_t off = SW128((a_row + m * 16) * 128 + kb16 + a_cb);
            ldmx4(Ahi[m], sbase + QK_QHI + off);
            ldmx4(Alo[m], sbase + QK_QLO + off);
        }
        uint32_t Bhi[2][4], Blo[2][4];
#pragma unroll
        for (int p = 0; p < 2; p++) {
            uint32_t off = SW128((b_row + p * 16) * 128 + kb16 + b_cb);
            ldmx4(Bhi[p], sbase + QK_KHI + off);
            ldmx4(Blo[p], sbase + QK_KLO + off);
        }
#pragma unroll
        for (int m = 0; m < 4; m++)
#pragma unroll
            for (int n = 0; n < 4; n++) {
                const uint32_t* bh2 = &Bhi[n >> 1][(n & 1) * 2];
                const uint32_t* bl2 = &Blo[n >> 1][(n & 1) * 2];
                mma16816bf(acc[m][n], Ahi[m], bh2);
                mma16816bf(acc[m][n], Ahi[m], bl2);
                mma16816bf(acc[m][n], Alo[m], bh2);
            }
    }

    // ---- epilogue: STS fp16 tile (pitch 272B), then coalesced uint4 STG
    __syncthreads();
    {
        const int er = (lane >> 2);
        const int ec = (lane & 3) * 2;
#pragma unroll
        for (int m = 0; m < 4; m++) {
            int row = wr * 64 + m * 16 + er;
#pragma unroll
            for (int n = 0; n < 4; n++) {
                int col = wc * 32 + n * 8 + ec;
                *(__half2*)(smem + row * EP_PITCH + col * 2) =
                    __floats2half2_rn(acc[m][n][0] * 0.125f, acc[m][n][1] * 0.125f);
                *(__half2*)(smem + (row + 8) * EP_PITCH + col * 2) =
                    __floats2half2_rn(acc[m][n][2] * 0.125f, acc[m][n][3] * 0.125f);
            }
        }
    }
    __syncthreads();
    {
        __half* sc = g_scores + ((size_t)bh * SEQ + q0) * SEQ + k0;
        const int r = tid >> 1;
        const int hf = tid & 1;
#pragma unroll
        for (int i = 0; i < 8; i++) {
            uint4 v = *(uint4*)(smem + r * EP_PITCH + hf * 128 + i * 16);
            *(uint4*)(sc + (size_t)r * SEQ + hf * 64 + i * 8) = v;
        }
    }
}

// ---------------------------------------------------------------------------
// Kernel 2 (FUSED softmax + AV, single-sync): CTA = (b, 32 q, all 16 heads),
// 512 threads = 16 warps, warp w = head w.
// Per 32-k chunk: issue score LDGs; stage V (WARP-PRIVATE plane -> no
// barrier needed, program order protects reuse); exp/normalize; write fp32
// attn + fp16 A into DOUBLE-BUFFERED A planes; ONE sync; MMA. Barrier slack
// lets fast warps run ahead one phase -> MUFU/LSU overlaps tensor across
// warps.
// smem: V planes 16 x 64 x 64B = 64KB; A planes 2 x 16 x 32 x 64B = 64KB.
// ---------------------------------------------------------------------------
#define FK 32
#define FV_STRIDE 4096u
#define FA_BASE   65536u
#define FA_BUFSZ  32768u
#define FA_STRIDE 2048u
#define FAV_SMEM  131072

__global__ __launch_bounds__(512) void softmax_av_fused_kernel(
    float* __restrict__ attn, float* __restrict__ out)
{
    extern __shared__ char smem[];
    uint32_t sbase = smem_u32(smem);
    const int tid = threadIdx.x;
    const int wid = tid >> 5;          // head
    const int lane = tid & 31;
    const int b  = blockIdx.y;
    const int q0 = blockIdx.x * 32;

    const int sq = tid >> 4;           // 0..31
    const int sk = (lane & 15) * 2;    // 0,2,..,30

    const size_t plane = (size_t)SEQ * SEQ;
    const __half* vt = g_vT_f16 + (size_t)(b * HH + wid) * DIM * SEQ;
    const __half* sc = g_scores + (size_t)b * HH * plane;
    float* ab = attn + (size_t)b * HH * plane;

    float acc[2][8][4];
#pragma unroll
    for (int m = 0; m < 2; m++)
#pragma unroll
        for (int n = 0; n < 8; n++)
#pragma unroll
            for (int i = 0; i < 4; i++) acc[m][n][i] = 0.0f;

    const int a_row = lane & 15;
    const int a_cb  = (lane >> 4) << 4;
    const int b_row = ((lane >> 4) << 3) + (lane & 7);
    const int b_cb  = ((lane >> 3) & 1) << 4;
    const uint32_t Vp = sbase + wid * FV_STRIDE;
    const uint32_t aoff = SW64X((uint32_t)(sq * 64 + sk * 2));

    for (int ic = 0; ic < SEQ / FK; ic++) {
        const int kc0 = ic * FK;
        const uint32_t abuf = FA_BASE + (uint32_t)(ic & 1) * FA_BUFSZ;

        // --- issue this chunk's score loads first (latency drains under
        //     the V staging below)
        float ex[HH][2];
        const size_t base = (size_t)(q0 + sq) * SEQ + kc0 + sk;
#pragma unroll
        for (int hh = 0; hh < HH; hh++) {
            float2 v = __half22float2(*(const __half2*)(sc + (size_t)hh * plane + base));
            ex[hh][0] = v.x; ex[hh][1] = v.y;
        }

        // --- stage this head's V chunk (warp-private plane, no barrier)
#pragma unroll
        for (int i = 0; i < 8; i++) {
            int idx = i * 32 + lane;
            int d = idx >> 2, j = idx & 3;
            uint4 v = *(const uint4*)(vt + (size_t)d * SEQ + kc0 + j * 8);
            *(uint4*)(smem + wid * FV_STRIDE + SW64X(d * 64 + j * 16)) = v;
        }

        // --- softmax over heads for this thread's 2 positions
        {
            float s0 = 0.0f, s1 = 0.0f;
#pragma unroll
            for (int hh = 0; hh < HH; hh++) {
                ex[hh][0] = __expf(ex[hh][0]);
                ex[hh][1] = __expf(ex[hh][1]);
                s0 += ex[hh][0];
                s1 += ex[hh][1];
            }
            const float i0 = 1.0f / s0, i1 = 1.0f / s1;
#pragma unroll
            for (int hh = 0; hh < HH; hh++) {
                float a0 = ex[hh][0] * i0;
                float a1 = ex[hh][1] * i1;
                *(__half2*)(smem + abuf + hh * FA_STRIDE + aoff) =
                    __floats2half2_rn(a0, a1);
                float2 w = { a0, a1 };
                *(float2*)(ab + (size_t)hh * plane + base) = w;
            }
        }
        __syncthreads();   // single barrier: A planes visible to all warps

        // --- MMA for this warp's head: A 32x32 @ V^T 64x32 -> 32x64
        const uint32_t Ap = sbase + abuf + wid * FA_STRIDE;
#pragma unroll
        for (int kc = 0; kc < 2; kc++) {
            uint32_t Ah[2][4];
#pragma unroll
            for (int m = 0; m < 2; m++)
                ldmx4(Ah[m], Ap + SW64X((m * 16 + a_row) * 64 + kc * 32 + a_cb));
            uint32_t Bh[4][4];
#pragma unroll
            for (int p = 0; p < 4; p++)
                ldmx4(Bh[p], Vp + SW64X((p * 16 + b_row) * 64 + kc * 32 + b_cb));
#pragma unroll
            for (int m = 0; m < 2; m++)
#pragma unroll
                for (int n = 0; n < 8; n++)
                    mma16816h(acc[m][n], Ah[m], &Bh[n >> 1][(n & 1) * 2]);
        }
        // no second barrier: next iter's A writes go to the other buffer,
        // whose previous readers (MMA of iter-1) are ordered by this iter's
        // barrier; V plane is warp-private (program order).
    }

    // --- epilogue: warp writes its head's out block (32q x 64d)
    float* ob = out + ((size_t)(b * HH + wid) * SEQ + q0) * DIM;
    const int er = lane >> 2;
    const int ec = (lane & 3) * 2;
#pragma unroll
    for (int m = 0; m < 2; m++) {
        int row = m * 16 + er;
#pragma unroll
        for (int n = 0; n < 8; n++) {
            int col = n * 8 + ec;
            float2 v0 = { acc[m][n][0], acc[m][n][1] };
            float2 v1 = { acc[m][n][2], acc[m][n][3] };
            *(float2*)(ob + (size_t)row * DIM + col) = v0;
            *(float2*)(ob + (size_t)(row + 8) * DIM + col) = v1;
        }
    }
}

// ---------------------------------------------------------------------------
// Launch: d_out = [ out (B*H*S*D) | attn (B*H*S*S) ]
// ---------------------------------------------------------------------------
extern "C" void kernel_launch(void* const* d_in, const int* in_sizes, int n_in,
                              void* d_out, int out_size)
{
    const float* q = (const float*)d_in[0];
    const float* k = (const float*)d_in[1];
    const float* v = (const float*)d_in[2];

    float* out  = (float*)d_out;
    float* attn = out + (size_t)BB * HH * SEQ * DIM;

    cudaFuncSetAttribute(qk_mma_kernel,
                         cudaFuncAttributeMaxDynamicSharedMemorySize, QK_SMEM);
    cudaFuncSetAttribute(softmax_av_fused_kernel,
                         cudaFuncAttributeMaxDynamicSharedMemorySize, FAV_SMEM);

    // 0) V transpose + fp16 convert
    {
        dim3 grid(SEQ / 32, DIM / 32, BH);
        vsplit_kernel<<<grid, 256>>>(v);
    }
    // 1) raw scores (fp16, coalesced) -> g_scores scratch
    {
        dim3 grid(SEQ / 128, SEQ / 128, BH);
        qk_mma_kernel<<<grid, 256, QK_SMEM>>>(q, k);
    }
    // 2) fused: softmax over heads (fp16 scores -> fp32 attn) + out = attn @ V
    {
        dim3 grid(SEQ / 32, BB);
        softmax_av_fused_kernel<<<grid, 512, FAV_SMEM>>>(attn, out);
    }
}